// round 2
// baseline (speedup 1.0000x reference)
#include <cuda_runtime.h>
#include <math.h>

#define VOC   50257
#define EMB   128
#define N_MEM 8192
#define T_Q   50
#define T_M   50
#define N_HOPS 3

#define NBH 512   // hop blocks
#define NBL 512   // logits blocks

// ---------------- scratch (device globals) ----------------
__device__ float g_min [N_MEM * EMB];
__device__ float g_mout[N_MEM * EMB];
__device__ float g_u[EMB];
__device__ float g_pmax[NBH];
__device__ float g_pden[NBH];
__device__ float g_pwsum[NBH * EMB];
__device__ float g_plmax[NBL];
__device__ float g_plden[NBL];

// ---------------- memory build (+ u0 in the extra block) ----------------
__global__ void k_mem(const int* __restrict__ story,
                      const float* __restrict__ Wa, const float* __restrict__ Wc,
                      const float* __restrict__ TA, const float* __restrict__ TC,
                      const int* __restrict__ q,  const float* __restrict__ Wb) {
    if (blockIdx.x == N_MEM / 4) {           // u0 block
        int e = threadIdx.x;
        float a = 0.f;
#pragma unroll 10
        for (int t = 0; t < T_Q; t++) a += Wb[(long)__ldg(q + t) * EMB + e];
        g_u[e] = a;
        return;
    }
    int gw   = blockIdx.x * 4 + (threadIdx.x >> 5);   // memory row
    int lane = threadIdx.x & 31;

    const float4* wa4 = (const float4*)Wa;
    const float4* wc4 = (const float4*)Wc;
    float4 ain  = ((const float4*)TA)[gw * 32 + lane];
    float4 aout = ((const float4*)TC)[gw * 32 + lane];
    const int* s = story + gw * T_M;

#pragma unroll 10
    for (int t = 0; t < T_M; t++) {
        int idx = __ldg(s + t);
        float4 a = wa4[(long)idx * 32 + lane];
        float4 c = wc4[(long)idx * 32 + lane];
        ain.x += a.x;  ain.y += a.y;  ain.z += a.z;  ain.w += a.w;
        aout.x += c.x; aout.y += c.y; aout.z += c.z; aout.w += c.w;
    }
    ((float4*)g_min )[gw * 32 + lane] = ain;
    ((float4*)g_mout)[gw * 32 + lane] = aout;
}

// ---------------- fused hop: online softmax + weighted sum, per-block partials ----------------
__global__ void k_hop() {
    __shared__ float4 su4[32];
    __shared__ float sm[8], sd[8];
    __shared__ float sacc[8 * EMB];
    int tid = threadIdx.x, lane = tid & 31, wid = tid >> 5;
    if (tid < 32) su4[tid] = ((const float4*)g_u)[tid];
    __syncthreads();
    float4 uu = su4[lane];

    int gw = (blockIdx.x * blockDim.x + tid) >> 5;
    int nw = (gridDim.x * blockDim.x) >> 5;

    float m = -INFINITY, d = 0.f;
    float4 acc = make_float4(0.f, 0.f, 0.f, 0.f);
    for (int n = gw; n < N_MEM; n += nw) {
        float4 mi = ((const float4*)(g_min  + n * EMB))[lane];
        float4 mo = ((const float4*)(g_mout + n * EMB))[lane];
        float p = mi.x * uu.x + mi.y * uu.y + mi.z * uu.z + mi.w * uu.w;
#pragma unroll
        for (int o = 16; o; o >>= 1) p += __shfl_xor_sync(0xFFFFFFFFu, p, o);
        float mn = fmaxf(m, p);
        float sc = __expf(m - mn);
        float w  = __expf(p - mn);
        d = d * sc + w;
        acc.x = acc.x * sc + w * mo.x;
        acc.y = acc.y * sc + w * mo.y;
        acc.z = acc.z * sc + w * mo.z;
        acc.w = acc.w * sc + w * mo.w;
        m = mn;
    }
    if (lane == 0) { sm[wid] = m; sd[wid] = d; }
    sacc[wid * EMB + lane * 4 + 0] = acc.x;
    sacc[wid * EMB + lane * 4 + 1] = acc.y;
    sacc[wid * EMB + lane * 4 + 2] = acc.z;
    sacc[wid * EMB + lane * 4 + 3] = acc.w;
    __syncthreads();

    if (tid < EMB) {
        float mb = sm[0];
#pragma unroll
        for (int w = 1; w < 8; w++) mb = fmaxf(mb, sm[w]);
        float v = 0.f;
#pragma unroll
        for (int w = 0; w < 8; w++) v += sacc[w * EMB + tid] * __expf(sm[w] - mb);
        g_pwsum[blockIdx.x * EMB + tid] = v;
        if (tid == 0) {
            float db = 0.f;
#pragma unroll
            for (int w = 0; w < 8; w++) db += sd[w] * __expf(sm[w] - mb);
            g_pmax[blockIdx.x] = mb;
            g_pden[blockIdx.x] = db;
        }
    }
}

// ---------------- combine partials + gated update ----------------
__global__ void k_update(const float* __restrict__ Wt_w, const float* __restrict__ Wt_b,
                         const float* __restrict__ H_w,  const float* __restrict__ H_b) {
    __shared__ float su[EMB], swo[EMB];
    int e = threadIdx.x;

    float M = -INFINITY;
#pragma unroll 8
    for (int b = 0; b < NBH; b++) M = fmaxf(M, g_pmax[b]);
    float wo = 0.f, den = 0.f;
#pragma unroll 4
    for (int b = 0; b < NBH; b++) {
        float s = __expf(g_pmax[b] - M);
        wo  += g_pwsum[b * EMB + e] * s;
        den += g_pden[b] * s;
    }
    su[e]  = g_u[e];
    swo[e] = wo / den;
    __syncthreads();

    float dt = 0.f, dh = 0.f;
    const float* wr = Wt_w + e * EMB;
    const float* hr = H_w  + e * EMB;
#pragma unroll 8
    for (int k = 0; k < EMB; k++) {
        dt += wr[k] * su[k];
        dh += hr[k] * swo[k];
    }
    float t = 1.f / (1.f + expf(-(dt + Wt_b[e])));
    g_u[e] = su[e] * (1.f - t) + (dh + H_b[e]) * t;
}

// ---------------- logits + fused online max/expsum partials ----------------
__global__ void k_logits(const float* __restrict__ wout, float* __restrict__ out) {
    __shared__ float4 su4[32];
    __shared__ float sm[8], sd[8];
    int tid = threadIdx.x, lane = tid & 31, wid = tid >> 5;
    if (tid < 32) su4[tid] = ((const float4*)g_u)[tid];
    __syncthreads();
    float4 uu = su4[lane];

    int gw = (blockIdx.x * blockDim.x + tid) >> 5;
    int nw = (gridDim.x * blockDim.x) >> 5;

    float m = -INFINITY, d = 0.f;
    for (int v = gw; v < VOC; v += nw) {
        float4 r = ((const float4*)(wout + (long)v * EMB))[lane];
        float p = r.x * uu.x + r.y * uu.y + r.z * uu.z + r.w * uu.w;
#pragma unroll
        for (int o = 16; o; o >>= 1) p += __shfl_xor_sync(0xFFFFFFFFu, p, o);
        if (lane == 0) out[v] = p;
        float mn = fmaxf(m, p);
        d = d * __expf(m - mn) + __expf(p - mn);
        m = mn;
    }
    if (lane == 0) { sm[wid] = m; sd[wid] = d; }
    __syncthreads();
    if (tid == 0) {
        float mb = sm[0];
#pragma unroll
        for (int w = 1; w < 8; w++) mb = fmaxf(mb, sm[w]);
        float db = 0.f;
#pragma unroll
        for (int w = 0; w < 8; w++) db += sd[w] * __expf(sm[w] - mb);
        g_plmax[blockIdx.x] = mb;
        g_plden[blockIdx.x] = db;
    }
}

// ---------------- combine + normalize ----------------
__global__ void k_norm(float* __restrict__ out) {
    float M = -INFINITY;
#pragma unroll 8
    for (int b = 0; b < NBL; b++) M = fmaxf(M, g_plmax[b]);
    float D = 0.f;
#pragma unroll 8
    for (int b = 0; b < NBL; b++) D += g_plden[b] * __expf(g_plmax[b] - M);
    float c = M + logf(D);
    for (int v = blockIdx.x * blockDim.x + threadIdx.x; v < VOC; v += gridDim.x * blockDim.x)
        out[v] -= c;
}

// ---------------- launch ----------------
extern "C" void kernel_launch(void* const* d_in, const int* in_sizes, int n_in,
                              void* d_out, int out_size) {
    const int*   query = (const int*)  d_in[0];
    const int*   story = (const int*)  d_in[1];
    const float* Wa    = (const float*)d_in[2];
    const float* Wc    = (const float*)d_in[3];
    const float* Wb    = (const float*)d_in[4];
    const float* Wt_w  = (const float*)d_in[5];
    const float* Wt_b  = (const float*)d_in[6];
    const float* H_w   = (const float*)d_in[7];
    const float* H_b   = (const float*)d_in[8];
    const float* wout  = (const float*)d_in[9];
    const float* TA    = (const float*)d_in[10];
    const float* TC    = (const float*)d_in[11];
    float* out = (float*)d_out;

    k_mem<<<N_MEM / 4 + 1, 128>>>(story, Wa, Wc, TA, TC, query, Wb);

    for (int h = 0; h < N_HOPS; h++) {
        k_hop   <<<NBH, 256>>>();
        k_update<<<1, EMB>>>(Wt_w, Wt_b, H_w, H_b);
    }

    k_logits<<<NBL, 256>>>(wout, out);
    k_norm  <<<148, 256>>>(out);
}

// round 3
// speedup vs baseline: 1.9984x; 1.9984x over previous
#include <cuda_runtime.h>
#include <math.h>

#define VOC   50257
#define EMB   128
#define N_MEM 8192
#define T_Q   50
#define T_M   50
#define N_HOPS 3
#define NB    148     // one-wave grid for hop/logits kernels

// ---------------- scratch (device globals) ----------------
__device__ float g_min [N_MEM * EMB];
__device__ float g_mout[N_MEM * EMB];
__device__ float g_uarr[4][EMB];             // u after each stage
__device__ float g_pmax [2][NB];             // double-buffered hop partials
__device__ float g_pden [2][NB];
__device__ float g_pwsum[2][NB * EMB];
__device__ float g_plmax[NB];
__device__ float g_plden[NB];

__device__ __forceinline__ float warp_dot(float4 a, float4 b) {
    float p = a.x * b.x + a.y * b.y + a.z * b.z + a.w * b.w;
#pragma unroll
    for (int o = 16; o; o >>= 1) p += __shfl_xor_sync(0xFFFFFFFFu, p, o);
    return p;
}

// combine previous hop's partials + gated update -> new u in snew (all blocks redundantly)
__device__ void combine_update(int rbuf, int uprev, int unew, bool storeU,
                               const float* __restrict__ Wt_w, const float* __restrict__ Wt_b,
                               const float* __restrict__ H_w,  const float* __restrict__ H_b,
                               float* su, float* swo, float* sdt, float* sdh, float* snew) {
    int tid = threadIdx.x, lane = tid & 31, wid = tid >> 5;

    if (tid < EMB) {
        const float* pm = g_pmax[rbuf];
        const float* pd = g_pden[rbuf];
        const float* pw = g_pwsum[rbuf];
        float M = -INFINITY;
#pragma unroll 4
        for (int b = 0; b < NB; b++) M = fmaxf(M, pm[b]);
        float wo = 0.f, den = 0.f;
#pragma unroll 4
        for (int b = 0; b < NB; b++) {
            float s = __expf(pm[b] - M);
            wo  += pw[b * EMB + tid] * s;
            den += pd[b] * s;
        }
        su[tid]  = g_uarr[uprev][tid];
        swo[tid] = wo / den;
    }
    __syncthreads();

    // matvecs: warps 0-3 -> dt = Wt_w . su ; warps 4-7 -> dh = H_w . swo
    {
        const float* W   = (wid < 4) ? Wt_w : H_w;
        const float* vec = (wid < 4) ? su : swo;
        float*       dst = (wid < 4) ? sdt : sdh;
        float4 v4 = ((const float4*)vec)[lane];
        int r0 = (wid & 3) * 32;
#pragma unroll 4
        for (int j = 0; j < 32; j++) {
            int row = r0 + j;
            float4 w4 = ((const float4*)(W + row * EMB))[lane];
            float p = warp_dot(w4, v4);
            if (lane == 0) dst[row] = p;
        }
    }
    __syncthreads();

    if (tid < EMB) {
        float t = 1.f / (1.f + expf(-(sdt[tid] + Wt_b[tid])));
        float un = su[tid] * (1.f - t) + (sdh[tid] + H_b[tid]) * t;
        snew[tid] = un;
        if (storeU && blockIdx.x == 0) g_uarr[unew][tid] = un;
    }
    __syncthreads();
}

// ---------------- memory build (+ u0 in the extra block) ----------------
__global__ void k_mem(const int* __restrict__ story,
                      const float* __restrict__ Wa, const float* __restrict__ Wc,
                      const float* __restrict__ TA, const float* __restrict__ TC,
                      const int* __restrict__ q,  const float* __restrict__ Wb) {
    if (blockIdx.x == N_MEM / 8) {           // u0 block
        int e = threadIdx.x;
        if (e < EMB) {
            float a = 0.f;
#pragma unroll 10
            for (int t = 0; t < T_Q; t++) a += Wb[(long)__ldg(q + t) * EMB + e];
            g_uarr[0][e] = a;
        }
        return;
    }
    int gw   = blockIdx.x * 8 + (threadIdx.x >> 5);   // memory row
    int lane = threadIdx.x & 31;

    const float4* wa4 = (const float4*)Wa;
    const float4* wc4 = (const float4*)Wc;
    float4 ain  = ((const float4*)TA)[gw * 32 + lane];
    float4 aout = ((const float4*)TC)[gw * 32 + lane];
    const int* s = story + gw * T_M;

#pragma unroll 10
    for (int t = 0; t < T_M; t++) {
        int idx = __ldg(s + t);
        float4 a = wa4[(long)idx * 32 + lane];
        float4 c = wc4[(long)idx * 32 + lane];
        ain.x += a.x;  ain.y += a.y;  ain.z += a.z;  ain.w += a.w;
        aout.x += c.x; aout.y += c.y; aout.z += c.z; aout.w += c.w;
    }
    ((float4*)g_min )[gw * 32 + lane] = ain;
    ((float4*)g_mout)[gw * 32 + lane] = aout;
}

// ---------------- fused hop: (combine+update) prelude + online softmax attention ----------------
__global__ void k_hop(int hop,
                      const float* __restrict__ Wt_w, const float* __restrict__ Wt_b,
                      const float* __restrict__ H_w,  const float* __restrict__ H_b) {
    __shared__ __align__(16) float su[EMB], swo[EMB], sdt[EMB], sdh[EMB], snew[EMB];
    __shared__ float sm[8], sd[8];
    __shared__ float sacc[8 * EMB];
    int tid = threadIdx.x, lane = tid & 31, wid = tid >> 5;

    if (hop == 0) {
        if (tid < EMB) snew[tid] = g_uarr[0][tid];
        __syncthreads();
    } else {
        combine_update((hop - 1) & 1, hop - 1, hop, true,
                       Wt_w, Wt_b, H_w, H_b, su, swo, sdt, sdh, snew);
    }
    float4 uu = ((const float4*)snew)[lane];

    int gw = (blockIdx.x * blockDim.x + tid) >> 5;
    int nw = (gridDim.x * blockDim.x) >> 5;

    float m = -INFINITY, d = 0.f;
    float4 acc = make_float4(0.f, 0.f, 0.f, 0.f);
#pragma unroll 2
    for (int n = gw; n < N_MEM; n += nw) {
        float4 mi = ((const float4*)(g_min  + n * EMB))[lane];
        float4 mo = ((const float4*)(g_mout + n * EMB))[lane];
        float p = warp_dot(mi, uu);
        float mn = fmaxf(m, p);
        float sc = __expf(m - mn);
        float w  = __expf(p - mn);
        d = d * sc + w;
        acc.x = acc.x * sc + w * mo.x;
        acc.y = acc.y * sc + w * mo.y;
        acc.z = acc.z * sc + w * mo.z;
        acc.w = acc.w * sc + w * mo.w;
        m = mn;
    }
    if (lane == 0) { sm[wid] = m; sd[wid] = d; }
    sacc[wid * EMB + lane * 4 + 0] = acc.x;
    sacc[wid * EMB + lane * 4 + 1] = acc.y;
    sacc[wid * EMB + lane * 4 + 2] = acc.z;
    sacc[wid * EMB + lane * 4 + 3] = acc.w;
    __syncthreads();

    int wbuf = hop & 1;
    if (tid < EMB) {
        float mb = sm[0];
#pragma unroll
        for (int w = 1; w < 8; w++) mb = fmaxf(mb, sm[w]);
        float v = 0.f;
#pragma unroll
        for (int w = 0; w < 8; w++) v += sacc[w * EMB + tid] * __expf(sm[w] - mb);
        g_pwsum[wbuf][blockIdx.x * EMB + tid] = v;
        if (tid == 0) {
            float db = 0.f;
#pragma unroll
            for (int w = 0; w < 8; w++) db += sd[w] * __expf(sm[w] - mb);
            g_pmax[wbuf][blockIdx.x] = mb;
            g_pden[wbuf][blockIdx.x] = db;
        }
    }
}

// ---------------- logits: final combine+update prelude, raw logits + online max/expsum ----------------
__global__ void k_logits(const float* __restrict__ Wt_w, const float* __restrict__ Wt_b,
                         const float* __restrict__ H_w,  const float* __restrict__ H_b,
                         const float* __restrict__ wout, float* __restrict__ out) {
    __shared__ __align__(16) float su[EMB], swo[EMB], sdt[EMB], sdh[EMB], snew[EMB];
    __shared__ float sm[8], sd[8];
    int tid = threadIdx.x, lane = tid & 31, wid = tid >> 5;

    combine_update((N_HOPS - 1) & 1, N_HOPS - 1, N_HOPS, false,
                   Wt_w, Wt_b, H_w, H_b, su, swo, sdt, sdh, snew);
    float4 uu = ((const float4*)snew)[lane];

    int gw = (blockIdx.x * blockDim.x + tid) >> 5;
    int nw = (gridDim.x * blockDim.x) >> 5;

    float m = -INFINITY, d = 0.f;
#pragma unroll 2
    for (int v = gw; v < VOC; v += nw) {
        float4 r = ((const float4*)(wout + (long)v * EMB))[lane];
        float p = warp_dot(r, uu);
        if (lane == 0) out[v] = p;
        float mn = fmaxf(m, p);
        d = d * __expf(m - mn) + __expf(p - mn);
        m = mn;
    }
    if (lane == 0) { sm[wid] = m; sd[wid] = d; }
    __syncthreads();
    if (tid == 0) {
        float mb = sm[0];
#pragma unroll
        for (int w = 1; w < 8; w++) mb = fmaxf(mb, sm[w]);
        float db = 0.f;
#pragma unroll
        for (int w = 0; w < 8; w++) db += sd[w] * __expf(sm[w] - mb);
        g_plmax[blockIdx.x] = mb;
        g_plden[blockIdx.x] = db;
    }
}

// ---------------- combine logits partials + normalize ----------------
__global__ void k_norm(float* __restrict__ out) {
    float M = -INFINITY;
#pragma unroll 4
    for (int b = 0; b < NB; b++) M = fmaxf(M, g_plmax[b]);
    float D = 0.f;
#pragma unroll 4
    for (int b = 0; b < NB; b++) D += g_plden[b] * __expf(g_plmax[b] - M);
    float c = M + logf(D);
    for (int v = blockIdx.x * blockDim.x + threadIdx.x; v < VOC; v += gridDim.x * blockDim.x)
        out[v] -= c;
}

// ---------------- launch ----------------
extern "C" void kernel_launch(void* const* d_in, const int* in_sizes, int n_in,
                              void* d_out, int out_size) {
    const int*   query = (const int*)  d_in[0];
    const int*   story = (const int*)  d_in[1];
    const float* Wa    = (const float*)d_in[2];
    const float* Wc    = (const float*)d_in[3];
    const float* Wb    = (const float*)d_in[4];
    const float* Wt_w  = (const float*)d_in[5];
    const float* Wt_b  = (const float*)d_in[6];
    const float* H_w   = (const float*)d_in[7];
    const float* H_b   = (const float*)d_in[8];
    const float* wout  = (const float*)d_in[9];
    const float* TA    = (const float*)d_in[10];
    const float* TC    = (const float*)d_in[11];
    float* out = (float*)d_out;

    k_mem<<<N_MEM / 8 + 1, 256>>>(story, Wa, Wc, TA, TC, query, Wb);

    for (int h = 0; h < N_HOPS; h++)
        k_hop<<<NB, 256>>>(h, Wt_w, Wt_b, H_w, H_b);

    k_logits<<<NB, 256>>>(Wt_w, Wt_b, H_w, H_b, wout, out);
    k_norm  <<<NB, 256>>>(out);
}

// round 4
// speedup vs baseline: 2.6331x; 1.3176x over previous
#include <cuda_runtime.h>
#include <math.h>

#define VOC    50257
#define EMB    128
#define N_MEM  8192
#define T_Q    50
#define T_M    50
#define N_HOPS 3

#define NBV  148            // blocks for VOC-streaming kernels
#define TBV  1024
#define NWV  (NBV * (TBV / 32))       // 4736 warps
#define ROWS_PV (VOC + N_MEM)         // pv rows + sTA rows

#define NBM  128            // blocks for memory-space kernel
#define TBM  64             // threads (= memories) per block

#define SHIFT 24.0f         // constant softmax shift (cancels exactly)

// ---------------- scratch ----------------
__device__ float g_u[EMB];
__device__ float g_pv[VOC];        // u . Wa[v]
__device__ float g_sTA[N_MEM];     // u . TA[n]
__device__ float g_cw[VOC];        // sum of attn weights per vocab token
__device__ float g_wo[EMB];        // weighted_out numerator accumulator
__device__ float g_den;            // softmax denominator (times e^-SHIFT)
__device__ float g_plmax[NBV];
__device__ float g_plden[NBV];

__device__ __forceinline__ float warp_dot(float4 a, float4 b) {
    float p = a.x * b.x + a.y * b.y + a.z * b.z + a.w * b.w;
#pragma unroll
    for (int o = 16; o; o >>= 1) p += __shfl_xor_sync(0xFFFFFFFFu, p, o);
    return p;
}

// ---------------- u0 = sum_t Wb[query[t]] ----------------
__global__ void k_u0(const int* __restrict__ q, const float* __restrict__ Wb) {
    int e = threadIdx.x;
    float a = 0.f;
#pragma unroll 10
    for (int t = 0; t < T_Q; t++) a += Wb[(long)__ldg(q + t) * EMB + e];
    g_u[e] = a;
}

// ---------------- pv[v] = u.Wa[v], sTA[n] = u.TA[n]; zero cw/wo/den ----------------
__global__ void k_pv(const float* __restrict__ Wa, const float* __restrict__ TA) {
    __shared__ float4 su4[32];
    int tid = threadIdx.x, lane = tid & 31, wid = tid >> 5;
    int gid = blockIdx.x * TBV + tid;
    if (gid < VOC) g_cw[gid] = 0.f;
    if (blockIdx.x == 0) {
        if (tid < EMB) g_wo[tid] = 0.f;
        if (tid == EMB) g_den = 0.f;
    }
    if (tid < 32) su4[tid] = ((const float4*)g_u)[tid];
    __syncthreads();
    float4 uu = su4[lane];

    int gw = blockIdx.x * 32 + wid;
    for (int r = gw; r < ROWS_PV; r += NWV) {
        const float4* src = (r < VOC) ? (const float4*)(Wa + (long)r * EMB)
                                      : (const float4*)(TA + (long)(r - VOC) * EMB);
        float p = warp_dot(src[lane], uu);
        if (lane == 0) {
            if (r < VOC) g_pv[r] = p;
            else         g_sTA[r - VOC] = p;
        }
    }
}

// ---------------- per-memory: score via pv gather, w=exp, denom, scatter cw, wTC ----------------
__global__ void k_hopmem(const int* __restrict__ story, const float* __restrict__ TC) {
    __shared__ int   sst[TBM * T_M];       // this block's story rows
    __shared__ float sw[TBM];              // attn weights (unnormalized)
    __shared__ float sred[TBM / 32];
    __shared__ float sacc[TBM / 32][EMB];
    int tid = threadIdx.x, lane = tid & 31, wid = tid >> 5;

    long base = (long)blockIdx.x * TBM * T_M;
#pragma unroll 4
    for (int i = tid; i < TBM * T_M; i += TBM) sst[i] = story[base + i];
    __syncthreads();

    int n = blockIdx.x * TBM + tid;
    float s = g_sTA[n];
#pragma unroll 10
    for (int t = 0; t < T_M; t++) s += g_pv[sst[tid * T_M + t]];
    float w = __expf(s - SHIFT);
    sw[tid] = w;

    // warp-reduce denom
    float d = w;
#pragma unroll
    for (int o = 16; o; o >>= 1) d += __shfl_xor_sync(0xFFFFFFFFu, d, o);
    if (lane == 0) sred[wid] = d;

    // scatter attn weight into cw
#pragma unroll 10
    for (int t = 0; t < T_M; t++) atomicAdd(&g_cw[sst[tid * T_M + t]], w);
    __syncthreads();

    if (tid == 0) {
        float db = 0.f;
#pragma unroll
        for (int i = 0; i < TBM / 32; i++) db += sred[i];
        atomicAdd(&g_den, db);
    }

    // wTC: warp per memory over this block's memories
    float4 acc = make_float4(0.f, 0.f, 0.f, 0.f);
    for (int j = wid; j < TBM; j += TBM / 32) {
        float wn = sw[j];
        float4 v = ((const float4*)(TC + (long)(blockIdx.x * TBM + j) * EMB))[lane];
        acc.x += wn * v.x; acc.y += wn * v.y; acc.z += wn * v.z; acc.w += wn * v.w;
    }
    sacc[wid][lane * 4 + 0] = acc.x;
    sacc[wid][lane * 4 + 1] = acc.y;
    sacc[wid][lane * 4 + 2] = acc.z;
    sacc[wid][lane * 4 + 3] = acc.w;
    __syncthreads();
    if (tid < EMB / 2) {   // 64 threads cover 128 entries, 2 each
#pragma unroll
        for (int k = 0; k < 2; k++) {
            int e = tid * 2 + k;
            float v = 0.f;
#pragma unroll
            for (int w2 = 0; w2 < TBM / 32; w2++) v += sacc[w2][e];
            atomicAdd(&g_wo[e], v);
        }
    }
}

// ---------------- wo += sum_v cw[v] * Wc[v] ----------------
__global__ void k_wo(const float* __restrict__ Wc) {
    __shared__ float sacc[32][EMB];   // 16 KB
    int tid = threadIdx.x, lane = tid & 31, wid = tid >> 5;

    float4 acc = make_float4(0.f, 0.f, 0.f, 0.f);
    int gw = blockIdx.x * 32 + wid;
    for (int r = gw; r < VOC; r += NWV) {
        float c = g_cw[r];                                    // broadcast
        float4 v = ((const float4*)(Wc + (long)r * EMB))[lane];
        acc.x += c * v.x; acc.y += c * v.y; acc.z += c * v.z; acc.w += c * v.w;
    }
    sacc[wid][lane * 4 + 0] = acc.x;
    sacc[wid][lane * 4 + 1] = acc.y;
    sacc[wid][lane * 4 + 2] = acc.z;
    sacc[wid][lane * 4 + 3] = acc.w;
    __syncthreads();
    if (tid < EMB) {
        float v = 0.f;
#pragma unroll
        for (int w2 = 0; w2 < 32; w2++) v += sacc[w2][tid];
        atomicAdd(&g_wo[tid], v);
    }
}

// ---------------- gated update of u ----------------
__global__ void k_update(const float* __restrict__ Wt_w, const float* __restrict__ Wt_b,
                         const float* __restrict__ H_w,  const float* __restrict__ H_b) {
    __shared__ __align__(16) float su[EMB], swo[EMB], sdt[EMB], sdh[EMB];
    int tid = threadIdx.x, lane = tid & 31, wid = tid >> 5;
    if (tid < EMB) {
        su[tid]  = g_u[tid];
        swo[tid] = g_wo[tid] / g_den;
    }
    __syncthreads();

    const float* W   = (wid < 4) ? Wt_w : H_w;
    const float* vec = (wid < 4) ? su : swo;
    float*       dst = (wid < 4) ? sdt : sdh;
    float4 v4 = ((const float4*)vec)[lane];
    int r0 = (wid & 3) * 32;
#pragma unroll 4
    for (int j = 0; j < 32; j++) {
        int row = r0 + j;
        float4 w4 = ((const float4*)(W + row * EMB))[lane];
        float p = warp_dot(w4, v4);
        if (lane == 0) dst[row] = p;
    }
    __syncthreads();
    if (tid < EMB) {
        float t = 1.f / (1.f + expf(-(sdt[tid] + Wt_b[tid])));
        g_u[tid] = su[tid] * (1.f - t) + (sdh[tid] + H_b[tid]) * t;
    }
}

// ---------------- logits + online max/expsum partials ----------------
__global__ void k_logits(const float* __restrict__ wout, float* __restrict__ out) {
    __shared__ float4 su4[32];
    __shared__ float sm[32], sd[32];
    int tid = threadIdx.x, lane = tid & 31, wid = tid >> 5;
    if (tid < 32) su4[tid] = ((const float4*)g_u)[tid];
    __syncthreads();
    float4 uu = su4[lane];

    float m = -INFINITY, d = 0.f;
    int gw = blockIdx.x * 32 + wid;
    for (int v = gw; v < VOC; v += NWV) {
        float4 r = ((const float4*)(wout + (long)v * EMB))[lane];
        float p = warp_dot(r, uu);
        if (lane == 0) out[v] = p;
        float mn = fmaxf(m, p);
        d = d * __expf(m - mn) + __expf(p - mn);
        m = mn;
    }
    if (lane == 0) { sm[wid] = m; sd[wid] = d; }
    __syncthreads();
    if (tid < 32) {
        float mm = sm[tid], dd = sd[tid];
#pragma unroll
        for (int o = 16; o; o >>= 1) {
            float mo = __shfl_xor_sync(0xFFFFFFFFu, mm, o);
            float dd_o = __shfl_xor_sync(0xFFFFFFFFu, dd, o);
            float mn = fmaxf(mm, mo);
            dd = dd * __expf(mm - mn) + dd_o * __expf(mo - mn);
            mm = mn;
        }
        if (tid == 0) { g_plmax[blockIdx.x] = mm; g_plden[blockIdx.x] = dd; }
    }
}

// ---------------- combine logits partials + normalize ----------------
__global__ void k_norm(float* __restrict__ out) {
    float M = -INFINITY;
#pragma unroll 4
    for (int b = 0; b < NBV; b++) M = fmaxf(M, g_plmax[b]);
    float D = 0.f;
#pragma unroll 4
    for (int b = 0; b < NBV; b++) D += g_plden[b] * __expf(g_plmax[b] - M);
    float c = M + logf(D);
    for (int v = blockIdx.x * blockDim.x + threadIdx.x; v < VOC; v += gridDim.x * blockDim.x)
        out[v] -= c;
}

// ---------------- launch ----------------
extern "C" void kernel_launch(void* const* d_in, const int* in_sizes, int n_in,
                              void* d_out, int out_size) {
    const int*   query = (const int*)  d_in[0];
    const int*   story = (const int*)  d_in[1];
    const float* Wa    = (const float*)d_in[2];
    const float* Wc    = (const float*)d_in[3];
    const float* Wb    = (const float*)d_in[4];
    const float* Wt_w  = (const float*)d_in[5];
    const float* Wt_b  = (const float*)d_in[6];
    const float* H_w   = (const float*)d_in[7];
    const float* H_b   = (const float*)d_in[8];
    const float* wout  = (const float*)d_in[9];
    const float* TA    = (const float*)d_in[10];
    const float* TC    = (const float*)d_in[11];
    float* out = (float*)d_out;

    k_u0<<<1, EMB>>>(query, Wb);

    for (int h = 0; h < N_HOPS; h++) {
        k_pv    <<<NBV, TBV>>>(Wa, TA);
        k_hopmem<<<NBM, TBM>>>(story, TC);
        k_wo    <<<NBV, TBV>>>(Wc);
        k_update<<<1, 256>>>(Wt_w, Wt_b, H_w, H_b);
    }

    k_logits<<<NBV, TBV>>>(wout, out);
    k_norm  <<<NBV, 256>>>(out);
}